// round 14
// baseline (speedup 1.0000x reference)
#include <cuda_runtime.h>
#include <cuda_fp16.h>
#include <cstdint>

constexpr int B_ = 8, T_ = 12, H_ = 96, W_ = 96, C_ = 32, F_ = 32;
constexpr int HW_ = H_ * W_;
constexpr int NTAP = 9;
constexpr int WPAD = 40;             // fp16 per weight row (80 B, 16B-aligned rows)
constexpr int CHB  = 128 * WPAD * 2; // 10240 B per weight chunk
constexpr int TAPB = 2 * CHB;        // 20480 B per tap stage (Wx, Wc)
constexpr int NSTAGE = 4;            // ring depth
constexpr int NTHR = 512;            // 16 warps: 4(m) x 4(n), CTA tile 256px x 128

// ---- device globals (allocation-free) ----
__device__ __align__(1024) __half g_Bw[NTAP * 2 * 128 * WPAD];  // fp16 weights (gate-blocked)
__device__ float g_h0[(size_t)B_ * HW_ * F_];
__device__ float g_h1[(size_t)B_ * HW_ * F_];
__device__ float g_c[(size_t)B_ * HW_ * F_];

// ---- smem map ----
constexpr int SM_FULL  = 8;                  // full[4]  @ 8..40
constexpr int SM_EMPTY = 40;                 // empty[4] @ 40..72
constexpr int TILE_SZ = 10 * 34 * 80;        // 27200 B (10 halo rows x 34 px x 80 B)
constexpr int SM_X    = 128;
constexpr int SM_H    = SM_X + TILE_SZ;      // 27328
constexpr int SM_W    = SM_X + 2 * TILE_SZ;  // 54528 (128-aligned)
constexpr int SMEM_TOTAL = SM_W + NSTAGE * TAPB;  // 136448 -> 1 CTA/SM
constexpr int SM_Z    = 128;                 // z tile (256 x 132 f32) overlays tiles+ring
constexpr int ZSTR    = 132;

// ---- PTX helpers ----
__device__ __forceinline__ uint32_t s2u(const void* p) {
    uint32_t a;
    asm("{ .reg .u64 t; cvta.to.shared.u64 t, %1; cvt.u32.u64 %0, t; }" : "=r"(a) : "l"(p));
    return a;
}
__device__ __forceinline__ void mbar_init(uint32_t a, uint32_t n) {
    asm volatile("mbarrier.init.shared.b64 [%0], %1;" :: "r"(a), "r"(n) : "memory");
}
__device__ __forceinline__ void mbar_expect(uint32_t a, uint32_t b) {
    asm volatile("mbarrier.arrive.expect_tx.shared.b64 _, [%0], %1;" :: "r"(a), "r"(b) : "memory");
}
__device__ __forceinline__ void mbar_arrive(uint32_t a) {
    asm volatile("mbarrier.arrive.shared.b64 _, [%0];" :: "r"(a) : "memory");
}
__device__ __forceinline__ void mbar_wait(uint32_t a, uint32_t ph) {
    asm volatile(
        "{\n\t.reg .pred P;\n\t"
        "W_%=:\n\t"
        "mbarrier.try_wait.parity.shared.b64 P, [%0], %1, 0x989680;\n\t"
        "@!P bra W_%=;\n\t}"
        :: "r"(a), "r"(ph) : "memory");
}
__device__ __forceinline__ void bulk_cp(uint32_t dst, const void* src, uint32_t bytes, uint32_t bar) {
    asm volatile(
        "cp.async.bulk.shared::cta.global.mbarrier::complete_tx::bytes [%0], [%1], %2, [%3];"
        :: "r"(dst), "l"(src), "r"(bytes), "r"(bar) : "memory");
}
__device__ __forceinline__ void ldmatrix4(uint32_t* a, uint32_t addr) {
    asm volatile("ldmatrix.sync.aligned.m8n8.x4.shared.b16 {%0,%1,%2,%3}, [%4];"
                 : "=r"(a[0]), "=r"(a[1]), "=r"(a[2]), "=r"(a[3]) : "r"(addr));
}
__device__ __forceinline__ void mma16816(float* d, const uint32_t* a, uint32_t b0, uint32_t b1) {
    asm volatile(
        "mma.sync.aligned.m16n8k16.row.col.f32.f16.f16.f32 "
        "{%0,%1,%2,%3}, {%4,%5,%6,%7}, {%8,%9}, {%0,%1,%2,%3};"
        : "+f"(d[0]), "+f"(d[1]), "+f"(d[2]), "+f"(d[3])
        : "r"(a[0]), "r"(a[1]), "r"(a[2]), "r"(a[3]), "r"(b0), "r"(b1));
}

// ---- prep: zero states + build fp16 weight stages (gate-blocked) ----
__global__ void prep_kernel(const float* __restrict__ Wx, const float* __restrict__ Wh) {
    int i = blockIdx.x * blockDim.x + threadIdx.x;
    if (i < B_ * HW_ * F_) { g_h0[i] = 0.f; g_c[i] = 0.f; }
    if (i < NTAP * 2 * 128 * 32) {
        int tap = i >> 13;
        int r = i & 8191;
        int src = r >> 12;
        int rr = r & 4095;
        int nn = rr >> 5;
        int ci = rr & 31;
        int widx = (tap * 32 + ci) * 128 + nn;
        float w = (src == 0) ? Wx[widx] : (Wx[widx] + Wh[widx]);
        g_Bw[(size_t)tap * (2 * 128 * WPAD) + src * (128 * WPAD) + nn * WPAD + ci] =
            __float2half_rn(w);
    }
}

// ---- fused step: 256px x 128gate CTA tile; 16 warps of 64x32 (R9 inner loop) ----
__global__ __launch_bounds__(NTHR, 1)
void lstm_step(const float* __restrict__ x, const float* __restrict__ bias,
               float* __restrict__ out, int t) {
    extern __shared__ __align__(1024) char smem[];
    const uint32_t sb = s2u(smem);
    const int tid = threadIdx.x;
    const int wid = tid >> 5, lid = tid & 31;
    const int warp_m = wid >> 2, warp_n = wid & 3;   // 4 x 4 warp grid
    const int bx = blockIdx.x, by = blockIdx.y, n = blockIdx.z;

    if (tid == 0) {
#pragma unroll
        for (int i = 0; i < NSTAGE; i++) {
            mbar_init(sb + SM_FULL + 8 * i, 1);
            mbar_init(sb + SM_EMPTY + 8 * i, 16);
        }
    }
    __syncthreads();

    // prologue: prefetch taps 0..3
    if (tid == 0) {
#pragma unroll
        for (int i = 0; i < NSTAGE; i++) {
            mbar_expect(sb + SM_FULL + 8 * i, TAPB);
            bulk_cp(sb + SM_W + i * TAPB, (const char*)g_Bw + (size_t)i * TAPB,
                    TAPB, sb + SM_FULL + 8 * i);
        }
    }

    const float* hin = (t & 1) ? g_h1 : g_h0;
    float* hout      = (t & 1) ? g_h0 : g_h1;
    const float* xim = x + ((size_t)(n * T_ + t) * HW_) * C_;
    const float* him = hin + (size_t)n * HW_ * C_;

    // stage x,h halo tiles (10 rows x 34 cols x 32 ci) fp16, row stride 80 B
    for (int idx = tid; idx < 10 * 34 * 8; idx += NTHR) {
        int r = idx / (34 * 8);
        int rem = idx - r * (34 * 8);
        int cx = rem >> 3, c4 = rem & 7;
        int gy = by * 8 - 1 + r, gx = bx * 32 - 1 + cx;
        float4 xv = make_float4(0.f, 0.f, 0.f, 0.f), hv = xv;
        if ((unsigned)gy < (unsigned)H_ && (unsigned)gx < (unsigned)W_) {
            size_t o = ((size_t)gy * W_ + gx) * C_ + c4 * 4;
            xv = *(const float4*)(xim + o);
            hv = *(const float4*)(him + o);
        }
        int eb = (r * 34 + cx) * 80 + c4 * 8;
        char* px_ = smem + SM_X + eb;
        char* ph_ = smem + SM_H + eb;
        *(__half2*)(px_)     = __halves2half2(__float2half_rn(xv.x), __float2half_rn(xv.y));
        *(__half2*)(px_ + 4) = __halves2half2(__float2half_rn(xv.z), __float2half_rn(xv.w));
        *(__half2*)(ph_)     = __halves2half2(__float2half_rn(hv.x), __float2half_rn(hv.y));
        *(__half2*)(ph_ + 4) = __halves2half2(__float2half_rn(hv.z), __float2half_rn(hv.w));
    }
    __syncthreads();

    // per-lane constant offsets (warp tile: 64 m x 32 n; m covers 256 px total)
    const int row_in_tile = ((lid >> 3) & 1) * 8 + (lid & 7);
    const int khalf = lid >> 4;
    uint32_t amt[4];
#pragma unroll
    for (int mt = 0; mt < 4; mt++) {
        int p = warp_m * 64 + mt * 16 + row_in_tile;   // 0..255
        amt[mt] = ((p >> 5) * 34 + (p & 31)) * 80 + khalf * 16;
    }
    const int m3 = lid >> 3;
    uint32_t bq[2];
#pragma unroll
    for (int q = 0; q < 2; q++)
        bq[q] = (uint32_t)((warp_n * 32 + (2 * q + (m3 >> 1)) * 8 + (lid & 7)) * (WPAD * 2) +
                           (m3 & 1) * 16);

    float d[4][4][4];
#pragma unroll
    for (int mt = 0; mt < 4; mt++)
#pragma unroll
        for (int nt = 0; nt < 4; nt++)
#pragma unroll
            for (int q = 0; q < 4; q++) d[mt][nt][q] = 0.f;

    // main loop over 9 taps; per tap: x @ Wx, then h @ Wc
    for (int tap = 0; tap < NTAP; tap++) {
        const int b = tap & 3;
        const uint32_t fullb = sb + SM_FULL + 8 * b;
        mbar_wait(fullb, (tap >> 2) & 1);

        const int dy = tap / 3, dx = tap - dy * 3;
        const uint32_t wbase = sb + SM_W + b * TAPB;
        const uint32_t aoff = (dy * 34 + dx) * 80;

#pragma unroll
        for (int part = 0; part < 2; part++) {
            const uint32_t abase = sb + (part ? SM_H : SM_X) + aoff;
            const uint32_t wp = wbase + part * CHB;
#pragma unroll
            for (int s = 0; s < 2; s++) {
                uint32_t af[4][4];
#pragma unroll
                for (int mt = 0; mt < 4; mt++)
                    ldmatrix4(af[mt], abase + amt[mt] + s * 32);
                uint32_t bh[2][4];
#pragma unroll
                for (int q = 0; q < 2; q++) ldmatrix4(bh[q], wp + bq[q] + s * 32);
#pragma unroll
                for (int nt = 0; nt < 4; nt++) {
                    uint32_t b0 = bh[nt >> 1][(nt & 1) * 2];
                    uint32_t b1 = bh[nt >> 1][(nt & 1) * 2 + 1];
#pragma unroll
                    for (int mt = 0; mt < 4; mt++) mma16816(d[mt][nt], af[mt], b0, b1);
                }
            }
        }

        if (lid == 0) mbar_arrive(sb + SM_EMPTY + 8 * b);
        if (tid == 0 && tap + NSTAGE < NTAP) {
            mbar_wait(sb + SM_EMPTY + 8 * b, (tap >> 2) & 1);
            mbar_expect(fullb, TAPB);
            bulk_cp(sb + SM_W + b * TAPB, (const char*)g_Bw + (size_t)(tap + NSTAGE) * TAPB,
                    TAPB, fullb);
        }
    }
    __syncthreads();  // ring/tiles dead -> safe to overwrite with z

    // stage z to smem (256 rows x stride 132 f32)
    float* zb = (float*)(smem + SM_Z);
#pragma unroll
    for (int mt = 0; mt < 4; mt++) {
        int prow = warp_m * 64 + mt * 16 + (lid >> 2);
#pragma unroll
        for (int nt = 0; nt < 4; nt++) {
            int col = warp_n * 32 + nt * 8 + 2 * (lid & 3);
            *(float2*)(zb + prow * ZSTR + col)       = make_float2(d[mt][nt][0], d[mt][nt][1]);
            *(float2*)(zb + (prow + 8) * ZSTR + col) = make_float2(d[mt][nt][2], d[mt][nt][3]);
        }
    }
    __syncthreads();

    // gates + state update; coalesced float4 I/O (2048 = 256 px * 8 f-groups)
#pragma unroll
    for (int j = 0; j < 4; j++) {
        int idx = j * NTHR + tid;
        int p = idx >> 3, fg = idx & 7;
        int gy = by * 8 + (p >> 5), gx = bx * 32 + (p & 31);
        const float* zr = zb + p * ZSTR + fg * 4;
        float4 zi = *(const float4*)(zr);
        float4 zf = *(const float4*)(zr + 32);
        float4 zc = *(const float4*)(zr + 64);
        float4 zo = *(const float4*)(zr + 96);
        float4 bi = *(const float4*)(bias + fg * 4);
        float4 bf = *(const float4*)(bias + 32 + fg * 4);
        float4 bc = *(const float4*)(bias + 64 + fg * 4);
        float4 bo = *(const float4*)(bias + 96 + fg * 4);
        size_t sbase = ((size_t)n * HW_ + (size_t)gy * W_ + gx) * F_ + fg * 4;
        float4 cold = *(const float4*)(g_c + sbase);

        float vi[4] = {zi.x + bi.x, zi.y + bi.y, zi.z + bi.z, zi.w + bi.w};
        float vf[4] = {zf.x + bf.x, zf.y + bf.y, zf.z + bf.z, zf.w + bf.w};
        float vc[4] = {zc.x + bc.x, zc.y + bc.y, zc.z + bc.z, zc.w + bc.w};
        float vo[4] = {zo.x + bo.x, zo.y + bo.y, zo.z + bo.z, zo.w + bo.w};
        const float* cp = (const float*)&cold;
        float cn[4], hn[4];
#pragma unroll
        for (int q = 0; q < 4; q++) {
            float ig = __saturatef(fmaf(0.2f, vi[q], 0.5f));
            float fgt = __saturatef(fmaf(0.2f, vf[q], 0.5f));
            float og = __saturatef(fmaf(0.2f, vo[q], 0.5f));
            float cv = fmaf(fgt, cp[q], ig * tanhf(vc[q]));
            cn[q] = cv;
            hn[q] = og * tanhf(cv);
        }
        float* outp = out + ((size_t)(n * T_ + t) * HW_ + (size_t)gy * W_ + gx) * F_ + fg * 4;
        *(float4*)(g_c + sbase)  = *(const float4*)(cn);
        *(float4*)(hout + sbase) = *(const float4*)(hn);
        *(float4*)(outp)         = *(const float4*)(hn);
    }
}

extern "C" void kernel_launch(void* const* d_in, const int* in_sizes, int n_in,
                              void* d_out, int out_size) {
    const float* x  = (const float*)d_in[0];
    const float* Wx = (const float*)d_in[1];
    const float* Wh = (const float*)d_in[2];
    const float* b  = (const float*)d_in[3];
    float* out = (float*)d_out;

    static bool attr_set = false;
    if (!attr_set) {
        cudaFuncSetAttribute(lstm_step, cudaFuncAttributeMaxDynamicSharedMemorySize,
                             SMEM_TOTAL);
        attr_set = true;
    }

    prep_kernel<<<(B_ * HW_ * F_ + 255) / 256, 256>>>(Wx, Wh);
    for (int t = 0; t < T_; t++)
        lstm_step<<<dim3(W_ / 32, H_ / 8, B_), NTHR, SMEM_TOTAL>>>(x, b, out, t);
}

// round 15
// speedup vs baseline: 1.0946x; 1.0946x over previous
#include <cuda_runtime.h>
#include <cuda_fp16.h>
#include <cstdint>

constexpr int B_ = 8, T_ = 12, H_ = 96, W_ = 96, C_ = 32, F_ = 32;
constexpr int HW_ = H_ * W_;
constexpr int NTAP = 9;
constexpr int WPAD = 40;             // fp16 per weight row (80 B, 16B-aligned rows)
constexpr int CHB  = 128 * WPAD * 2; // 10240 B per weight chunk
constexpr int TAPB = 2 * CHB;        // 20480 B per tap stage (Wx, Wc)
constexpr int NSTAGE = 4;            // ring depth

// ---- device globals (allocation-free) ----
__device__ __align__(1024) __half g_Bw[NTAP * 2 * 128 * WPAD];  // fp16 weights (gate-blocked)
__device__ float g_c[(size_t)B_ * HW_ * F_];

// ---- smem map (R9 layout) ----
constexpr int SM_FULL  = 8;                  // full[4]  @ 8..40
constexpr int SM_EMPTY = 40;                 // empty[4] @ 40..72
constexpr int SM_X    = 128;                 // fp16(x) tile, 6*34 rows x 80 B
constexpr int SM_H    = SM_X + 16384;        // fp16(h) tile
constexpr int SM_W    = SM_H + 16384;        // ring: 4 stages x 20480
constexpr int SMEM_TOTAL = SM_W + NSTAGE * TAPB;  // 114816 (2 CTAs/SM)
constexpr int SM_Z    = 128;                 // z tile overlays tiles+ring after MMA
constexpr int ZSTR    = 132;

// ---- PTX helpers ----
__device__ __forceinline__ uint32_t s2u(const void* p) {
    uint32_t a;
    asm("{ .reg .u64 t; cvta.to.shared.u64 t, %1; cvt.u32.u64 %0, t; }" : "=r"(a) : "l"(p));
    return a;
}
__device__ __forceinline__ void mbar_init(uint32_t a, uint32_t n) {
    asm volatile("mbarrier.init.shared.b64 [%0], %1;" :: "r"(a), "r"(n) : "memory");
}
__device__ __forceinline__ void mbar_expect(uint32_t a, uint32_t b) {
    asm volatile("mbarrier.arrive.expect_tx.shared.b64 _, [%0], %1;" :: "r"(a), "r"(b) : "memory");
}
__device__ __forceinline__ void mbar_arrive(uint32_t a) {
    asm volatile("mbarrier.arrive.shared.b64 _, [%0];" :: "r"(a) : "memory");
}
__device__ __forceinline__ void mbar_wait(uint32_t a, uint32_t ph) {
    asm volatile(
        "{\n\t.reg .pred P;\n\t"
        "W_%=:\n\t"
        "mbarrier.try_wait.parity.shared.b64 P, [%0], %1, 0x989680;\n\t"
        "@!P bra W_%=;\n\t}"
        :: "r"(a), "r"(ph) : "memory");
}
__device__ __forceinline__ void bulk_cp(uint32_t dst, const void* src, uint32_t bytes, uint32_t bar) {
    asm volatile(
        "cp.async.bulk.shared::cta.global.mbarrier::complete_tx::bytes [%0], [%1], %2, [%3];"
        :: "r"(dst), "l"(src), "r"(bytes), "r"(bar) : "memory");
}
__device__ __forceinline__ void ldmatrix4(uint32_t* a, uint32_t addr) {
    asm volatile("ldmatrix.sync.aligned.m8n8.x4.shared.b16 {%0,%1,%2,%3}, [%4];"
                 : "=r"(a[0]), "=r"(a[1]), "=r"(a[2]), "=r"(a[3]) : "r"(addr));
}
__device__ __forceinline__ void mma16816(float* d, const uint32_t* a, uint32_t b0, uint32_t b1) {
    asm volatile(
        "mma.sync.aligned.m16n8k16.row.col.f32.f16.f16.f32 "
        "{%0,%1,%2,%3}, {%4,%5,%6,%7}, {%8,%9}, {%0,%1,%2,%3};"
        : "+f"(d[0]), "+f"(d[1]), "+f"(d[2]), "+f"(d[3])
        : "r"(a[0]), "r"(a[1]), "r"(a[2]), "r"(a[3]), "r"(b0), "r"(b1));
}

// fragment-set helpers (R9 tiling: warp tile 64m x 32n)
__device__ __forceinline__ void ldsetA(uint32_t (&af)[4][4], uint32_t base,
                                       const uint32_t* amt, int s) {
#pragma unroll
    for (int mt = 0; mt < 4; mt++) ldmatrix4(af[mt], base + amt[mt] + s * 32);
}
__device__ __forceinline__ void ldsetB(uint32_t (&bh)[2][4], uint32_t wp,
                                       const uint32_t* bq, int s) {
#pragma unroll
    for (int q = 0; q < 2; q++) ldmatrix4(bh[q], wp + bq[q] + s * 32);
}
__device__ __forceinline__ void mmaset(float (&d)[4][4][4], const uint32_t (&af)[4][4],
                                       const uint32_t (&bh)[2][4]) {
#pragma unroll
    for (int nt = 0; nt < 4; nt++) {
        uint32_t b0 = bh[nt >> 1][(nt & 1) * 2];
        uint32_t b1 = bh[nt >> 1][(nt & 1) * 2 + 1];
#pragma unroll
        for (int mt = 0; mt < 4; mt++) mma16816(d[mt][nt], af[mt], b0, b1);
    }
}

// ---- prep: zero c + build fp16 weight stages (gate-blocked) ----
__global__ void prep_kernel(const float* __restrict__ Wx, const float* __restrict__ Wh) {
    int i = blockIdx.x * blockDim.x + threadIdx.x;
    if (i < B_ * HW_ * F_) g_c[i] = 0.f;
    if (i < NTAP * 2 * 128 * 32) {
        int tap = i >> 13;
        int r = i & 8191;
        int src = r >> 12;
        int rr = r & 4095;
        int nn = rr >> 5;
        int ci = rr & 31;
        int widx = (tap * 32 + ci) * 128 + nn;
        float w = (src == 0) ? Wx[widx] : (Wx[widx] + Wh[widx]);
        g_Bw[(size_t)tap * (2 * 128 * WPAD) + src * (128 * WPAD) + nn * WPAD + ci] =
            __float2half_rn(w);
    }
}

// ---- fused step (R9 shape + software-pipelined inner loop + h aliased to out) ----
__global__ __launch_bounds__(256, 2)
void lstm_step(const float* __restrict__ x, const float* __restrict__ bias,
               float* __restrict__ out, int t) {
    extern __shared__ __align__(1024) char smem[];
    const uint32_t sb = s2u(smem);
    const int tid = threadIdx.x;
    const int wid = tid >> 5, lid = tid & 31;
    const int warp_m = wid >> 2, warp_n = wid & 3;
    const int bx = blockIdx.x, by = blockIdx.y, n = blockIdx.z;

    if (tid == 0) {
#pragma unroll
        for (int i = 0; i < NSTAGE; i++) {
            mbar_init(sb + SM_FULL + 8 * i, 1);
            mbar_init(sb + SM_EMPTY + 8 * i, 8);
        }
    }
    __syncthreads();

    if (tid == 0) {
#pragma unroll
        for (int i = 0; i < NSTAGE; i++) {
            mbar_expect(sb + SM_FULL + 8 * i, TAPB);
            bulk_cp(sb + SM_W + i * TAPB, (const char*)g_Bw + (size_t)i * TAPB,
                    TAPB, sb + SM_FULL + 8 * i);
        }
    }

    const float* xim = x + ((size_t)(n * T_ + t) * HW_) * C_;
    const float* him = out + ((size_t)(n * T_ + (t - 1)) * HW_) * F_;  // h(t-1) lives in out
    const bool h0 = (t == 0);

    // stage x,h halo tiles (6 rows x 34 cols x 32 ci) fp16, row stride 80 B
    for (int idx = tid; idx < 6 * 34 * 8; idx += 256) {
        int r = idx / (34 * 8);
        int rem = idx - r * (34 * 8);
        int cx = rem >> 3, c4 = rem & 7;
        int gy = by * 4 - 1 + r, gx = bx * 32 - 1 + cx;
        float4 xv = make_float4(0.f, 0.f, 0.f, 0.f), hv = xv;
        if ((unsigned)gy < (unsigned)H_ && (unsigned)gx < (unsigned)W_) {
            size_t o = ((size_t)gy * W_ + gx) * C_ + c4 * 4;
            xv = *(const float4*)(xim + o);
            if (!h0) hv = *(const float4*)(him + o);
        }
        int eb = (r * 34 + cx) * 80 + c4 * 8;
        char* px_ = smem + SM_X + eb;
        char* ph_ = smem + SM_H + eb;
        *(__half2*)(px_)     = __halves2half2(__float2half_rn(xv.x), __float2half_rn(xv.y));
        *(__half2*)(px_ + 4) = __halves2half2(__float2half_rn(xv.z), __float2half_rn(xv.w));
        *(__half2*)(ph_)     = __halves2half2(__float2half_rn(hv.x), __float2half_rn(hv.y));
        *(__half2*)(ph_ + 4) = __halves2half2(__float2half_rn(hv.z), __float2half_rn(hv.w));
    }
    __syncthreads();

    // per-lane constant offsets
    const int row_in_tile = ((lid >> 3) & 1) * 8 + (lid & 7);
    const int khalf = lid >> 4;
    uint32_t amt[4];
#pragma unroll
    for (int mt = 0; mt < 4; mt++) {
        int p = warp_m * 64 + mt * 16 + row_in_tile;
        amt[mt] = ((p >> 5) * 34 + (p & 31)) * 80 + khalf * 16;
    }
    const int m3 = lid >> 3;
    uint32_t bq[2];
#pragma unroll
    for (int q = 0; q < 2; q++)
        bq[q] = (uint32_t)((warp_n * 32 + (2 * q + (m3 >> 1)) * 8 + (lid & 7)) * (WPAD * 2) +
                           (m3 & 1) * 16);

    float d[4][4][4];
#pragma unroll
    for (int mt = 0; mt < 4; mt++)
#pragma unroll
        for (int nt = 0; nt < 4; nt++)
#pragma unroll
            for (int q = 0; q < 4; q++) d[mt][nt][q] = 0.f;

    // ---- software-pipelined main loop ----
    // sets per tap: 0=(x,s0) 1=(x,s1) 2=(h,s0) 3=(h,s1); double-buffered fragments.
    uint32_t afb[2][4][4], bhb[2][2][4];

    // prologue: tap 0 set 0
    mbar_wait(sb + SM_FULL + 0, 0);
    ldsetA(afb[0], sb + SM_X, amt, 0);
    ldsetB(bhb[0], sb + SM_W, bq, 0);

    for (int tap = 0; tap < NTAP; tap++) {
        const int b = tap & 3;
        const int dy = tap / 3, dx = tap - dy * 3;
        const uint32_t aoff = (dy * 34 + dx) * 80;
        const uint32_t ax = sb + SM_X + aoff;
        const uint32_t ah = sb + SM_H + aoff;
        const uint32_t wp0 = sb + SM_W + b * TAPB;
        const uint32_t wp1 = wp0 + CHB;

        // set1 loads, set0 MMA
        ldsetA(afb[1], ax, amt, 1);
        ldsetB(bhb[1], wp0, bq, 1);
        mmaset(d, afb[0], bhb[0]);
        // set2 loads, set1 MMA
        ldsetA(afb[0], ah, amt, 0);
        ldsetB(bhb[0], wp1, bq, 0);
        mmaset(d, afb[1], bhb[1]);
        // set3 loads (last reads of stage b)
        ldsetA(afb[1], ah, amt, 1);
        ldsetB(bhb[1], wp1, bq, 1);
        if (lid == 0) mbar_arrive(sb + SM_EMPTY + 8 * b);
        if (tid == 0 && tap + NSTAGE < NTAP) {
            mbar_wait(sb + SM_EMPTY + 8 * b, (tap >> 2) & 1);
            mbar_expect(sb + SM_FULL + 8 * b, TAPB);
            bulk_cp(wp0, (const char*)g_Bw + (size_t)(tap + NSTAGE) * TAPB,
                    TAPB, sb + SM_FULL + 8 * b);
        }
        // set2 MMA; then prefetch next tap's set0 under set3 MMA
        mmaset(d, afb[0], bhb[0]);
        if (tap + 1 < NTAP) {
            const int nb = (tap + 1) & 3;
            mbar_wait(sb + SM_FULL + 8 * nb, ((tap + 1) >> 2) & 1);
            const int ndy = (tap + 1) / 3, ndx = (tap + 1) - ndy * 3;
            ldsetA(afb[0], sb + SM_X + (ndy * 34 + ndx) * 80, amt, 0);
            ldsetB(bhb[0], sb + SM_W + nb * TAPB, bq, 0);
        }
        mmaset(d, afb[1], bhb[1]);
    }
    __syncthreads();  // ring/tiles dead -> safe to overwrite with z

    // stage z to smem
    float* zb = (float*)(smem + SM_Z);
#pragma unroll
    for (int mt = 0; mt < 4; mt++) {
        int prow = warp_m * 64 + mt * 16 + (lid >> 2);
#pragma unroll
        for (int nt = 0; nt < 4; nt++) {
            int col = warp_n * 32 + nt * 8 + 2 * (lid & 3);
            *(float2*)(zb + prow * ZSTR + col)       = make_float2(d[mt][nt][0], d[mt][nt][1]);
            *(float2*)(zb + (prow + 8) * ZSTR + col) = make_float2(d[mt][nt][2], d[mt][nt][3]);
        }
    }
    __syncthreads();

    // gates + state update; coalesced float4 I/O
    const bool last = (t == T_ - 1);
#pragma unroll
    for (int j = 0; j < 4; j++) {
        int idx = j * 256 + tid;          // 1024 = 128 px * 8 f-groups
        int p = idx >> 3, fg = idx & 7;
        int gy = by * 4 + (p >> 5), gx = bx * 32 + (p & 31);
        const float* zr = zb + p * ZSTR + fg * 4;
        float4 zi = *(const float4*)(zr);
        float4 zf = *(const float4*)(zr + 32);
        float4 zc = *(const float4*)(zr + 64);
        float4 zo = *(const float4*)(zr + 96);
        float4 bi = *(const float4*)(bias + fg * 4);
        float4 bf = *(const float4*)(bias + 32 + fg * 4);
        float4 bc = *(const float4*)(bias + 64 + fg * 4);
        float4 bo = *(const float4*)(bias + 96 + fg * 4);
        size_t sbase = ((size_t)n * HW_ + (size_t)gy * W_ + gx) * F_ + fg * 4;
        float4 cold = *(const float4*)(g_c + sbase);

        float vi[4] = {zi.x + bi.x, zi.y + bi.y, zi.z + bi.z, zi.w + bi.w};
        float vf[4] = {zf.x + bf.x, zf.y + bf.y, zf.z + bf.z, zf.w + bf.w};
        float vc[4] = {zc.x + bc.x, zc.y + bc.y, zc.z + bc.z, zc.w + bc.w};
        float vo[4] = {zo.x + bo.x, zo.y + bo.y, zo.z + bo.z, zo.w + bo.w};
        const float* cp = (const float*)&cold;
        float cn[4], hn[4];
#pragma unroll
        for (int q = 0; q < 4; q++) {
            float ig = __saturatef(fmaf(0.2f, vi[q], 0.5f));
            float fgt = __saturatef(fmaf(0.2f, vf[q], 0.5f));
            float og = __saturatef(fmaf(0.2f, vo[q], 0.5f));
            float cv = fmaf(fgt, cp[q], ig * tanhf(vc[q]));
            cn[q] = cv;
            hn[q] = og * tanhf(cv);
        }
        float* outp = out + ((size_t)(n * T_ + t) * HW_ + (size_t)gy * W_ + gx) * F_ + fg * 4;
        if (!last) *(float4*)(g_c + sbase) = *(const float4*)(cn);
        *(float4*)(outp) = *(const float4*)(hn);
    }
}

extern "C" void kernel_launch(void* const* d_in, const int* in_sizes, int n_in,
                              void* d_out, int out_size) {
    const float* x  = (const float*)d_in[0];
    const float* Wx = (const float*)d_in[1];
    const float* Wh = (const float*)d_in[2];
    const float* b  = (const float*)d_in[3];
    float* out = (float*)d_out;

    static bool attr_set = false;
    if (!attr_set) {
        cudaFuncSetAttribute(lstm_step, cudaFuncAttributeMaxDynamicSharedMemorySize,
                             SMEM_TOTAL);
        attr_set = true;
    }

    prep_kernel<<<(B_ * HW_ * F_ + 255) / 256, 256>>>(Wx, Wh);
    for (int t = 0; t < T_; t++)
        lstm_step<<<dim3(W_ / 32, H_ / 4, B_), 256, SMEM_TOTAL>>>(x, b, out, t);
}